// round 3
// baseline (speedup 1.0000x reference)
#include <cuda_runtime.h>
#include <math.h>

#define IMGS 64
#define H 512
#define W 512
#define HW (H*W)
#define WORDS 16          // 512 bits / 32 per row
#define HD_STRIDE 17      // padded stride (words) to avoid smem bank conflicts

// ---------------- scratch (static device globals; no allocation) ----------------
__device__ unsigned char g_gray[(size_t)IMGS * HW];          // 16 MB
__device__ unsigned int  g_weak[(size_t)IMGS * H * WORDS];   // 2 MB
__device__ unsigned int  g_strong[(size_t)IMGS * H * WORDS]; // 2 MB
__device__ double        g_stats[IMGS * 8];                  // str, ang, ang2, lap, lap2
__device__ unsigned int  g_counts[IMGS * 2];                 // edge_count, dil_count

// ---------------- kernel 1: grayscale (exact, matches jnp.round semantics) ------
__device__ __forceinline__ float gray_of(float r, float g, float b) {
    // u8 = rint(clip(x,0,1)*255); gray = rint(0.299 r + 0.587 g + 0.114 b)
    // explicit round-to-nearest ops to prevent FMA contraction (bitwise match)
    float R  = rintf(__fmul_rn(__saturatef(r), 255.0f));
    float G  = rintf(__fmul_rn(__saturatef(g), 255.0f));
    float Bv = rintf(__fmul_rn(__saturatef(b), 255.0f));
    float y  = __fadd_rn(__fadd_rn(__fmul_rn(0.299f, R), __fmul_rn(0.587f, G)),
                         __fmul_rn(0.114f, Bv));
    return rintf(y);
}

__global__ void __launch_bounds__(256) k_gray(const float* __restrict__ x) {
    int tid = threadIdx.x;
    if (blockIdx.x == 0) {             // zero per-image stat accumulators each run
        g_stats[tid]       = 0.0;
        g_stats[tid + 256] = 0.0;
    }
    long long gid = (long long)blockIdx.x * 256 + tid;
    long long p4  = gid * 4;
    if (p4 >= (long long)IMGS * HW) return;
    int img = (int)(p4 / HW);
    int i   = (int)(p4 % HW);
    const float* base = x + (long long)img * 3 * HW;
    float4 r4 = *reinterpret_cast<const float4*>(base + i);
    float4 g4 = *reinterpret_cast<const float4*>(base + HW + i);
    float4 b4 = *reinterpret_cast<const float4*>(base + 2 * HW + i);
    uchar4 o;
    o.x = (unsigned char)gray_of(r4.x, g4.x, b4.x);
    o.y = (unsigned char)gray_of(r4.y, g4.y, b4.y);
    o.z = (unsigned char)gray_of(r4.z, g4.z, b4.z);
    o.w = (unsigned char)gray_of(r4.w, g4.w, b4.w);
    *reinterpret_cast<uchar4*>(g_gray + (size_t)img * HW + i) = o;
}

// ---------------- kernel 2: Sobel / NMS / per-image statistics -------------------
// One block = 32x32 output tile; block (32,8), 4 rows per thread.
__global__ void __launch_bounds__(256) k_sobel() {
    const int bx = blockIdx.x, by = blockIdx.y, img = blockIdx.z;
    const int x0 = bx * 32, y0 = by * 32;
    const int tx = threadIdx.x;
    const int tid = threadIdx.y * 32 + tx;

    __shared__ float sg[36][37];    // gray with halo 2 (reflect-101 applied)
    __shared__ float smag[34][35];  // |gx|+|gy| with halo 1 (0 outside image)
    __shared__ float sgx[34][35];
    __shared__ float sgy[34][35];
    __shared__ double red[8][5];

    const unsigned char* gp = g_gray + (size_t)img * HW;

    for (int t = tid; t < 36 * 36; t += 256) {
        int ly = t / 36, lx = t % 36;
        int iy = y0 - 2 + ly, ix = x0 - 2 + lx;
        iy = iy < 0 ? -iy : (iy > 511 ? 1022 - iy : iy);   // BORDER_REFLECT_101
        ix = ix < 0 ? -ix : (ix > 511 ? 1022 - ix : ix);
        sg[ly][lx] = (float)gp[iy * 512 + ix];
    }
    __syncthreads();

    for (int t = tid; t < 34 * 34; t += 256) {
        int my = t / 34, mx = t % 34;
        int iy = y0 - 1 + my, ix = x0 - 1 + mx;
        int ly = my + 1, lx = mx + 1;
        float a = sg[ly-1][lx-1], b = sg[ly-1][lx], c = sg[ly-1][lx+1];
        float d = sg[ly  ][lx-1],                   e = sg[ly  ][lx+1];
        float f = sg[ly+1][lx-1], g = sg[ly+1][lx], h = sg[ly+1][lx+1];
        float gx = (c - a) + 2.0f * (e - d) + (h - f);           // SOBEL_X corr
        float gy = (f + 2.0f * g + h) - (a + 2.0f * b + c);      // SOBEL_Y corr
        bool inside = (iy >= 0) & (iy < 512) & (ix >= 0) & (ix < 512);
        smag[my][mx] = inside ? (fabsf(gx) + fabsf(gy)) : 0.0f;  // zero-pad shift
        sgx[my][mx] = gx;
        sgy[my][mx] = gy;
    }
    __syncthreads();

    float s_str = 0.f, s_ang = 0.f, s_ang2 = 0.f, s_lap = 0.f, s_lap2 = 0.f;

    #pragma unroll
    for (int rr = 0; rr < 4; rr++) {
        int ty = threadIdx.y + rr * 8;
        int ly = ty + 2, lx = tx + 2;
        int my = ty + 1, mx = tx + 1;
        float gx = sgx[my][mx], gy = sgy[my][mx];
        float mag = smag[my][mx];
        float ang = atan2f(gy, gx);
        float str = sqrtf(gx * gx + gy * gy);
        float lap = sg[ly-1][lx] + sg[ly+1][lx] + sg[ly][lx-1] + sg[ly][lx+1]
                  - 4.0f * sg[ly][lx];
        s_str += str; s_ang += ang; s_ang2 += ang * ang;
        s_lap += lap; s_lap2 += lap * lap;

        float adeg = ang * 57.29577951308232f;   // (float)(180/pi), as JAX
        if (adeg < 0.0f) adeg += 180.0f;         // jnp.mod(.,180) for range (-180,180]
        float n1, n2;
        if (adeg < 22.5f || adeg >= 157.5f) { n1 = smag[my][mx+1];   n2 = smag[my][mx-1]; }
        else if (adeg < 67.5f)              { n1 = smag[my-1][mx+1]; n2 = smag[my+1][mx-1]; }
        else if (adeg < 112.5f)             { n1 = smag[my-1][mx];   n2 = smag[my+1][mx]; }
        else                                { n1 = smag[my-1][mx-1]; n2 = smag[my+1][mx+1]; }
        bool pass = (mag >= n1) && (mag >= n2);   // exact integer comparisons

        unsigned wb = __ballot_sync(0xffffffffu, pass && (mag >= 50.0f));
        unsigned sb = __ballot_sync(0xffffffffu, pass && (mag >= 150.0f));
        if (tx == 0) {
            int iy = y0 + ty;
            g_weak  [(size_t)img * H * WORDS + iy * WORDS + bx] = wb;
            g_strong[(size_t)img * H * WORDS + iy * WORDS + bx] = sb;
        }
    }

    // block reduction of 5 stats (double) -> 5 atomics per block
    double d0 = s_str, d1 = s_ang, d2 = s_ang2, d3 = s_lap, d4 = s_lap2;
    #pragma unroll
    for (int off = 16; off; off >>= 1) {
        d0 += __shfl_down_sync(0xffffffffu, d0, off);
        d1 += __shfl_down_sync(0xffffffffu, d1, off);
        d2 += __shfl_down_sync(0xffffffffu, d2, off);
        d3 += __shfl_down_sync(0xffffffffu, d3, off);
        d4 += __shfl_down_sync(0xffffffffu, d4, off);
    }
    if (tx == 0) {
        red[threadIdx.y][0] = d0; red[threadIdx.y][1] = d1; red[threadIdx.y][2] = d2;
        red[threadIdx.y][3] = d3; red[threadIdx.y][4] = d4;
    }
    __syncthreads();
    if (tid < 5) {
        double s = 0.0;
        #pragma unroll
        for (int wi = 0; wi < 8; wi++) s += red[wi][tid];
        atomicAdd(&g_stats[img * 8 + tid], s);
    }
}

// ---------------- kernel 3: hysteresis (16 Jacobi iters) + edge counts ----------
// One CTA per image; thread r owns row r. edges & weak live in registers as bits,
// only the horizontal-dilation pass goes through smem (Jacobi-safe with 2 bars).
__global__ void __launch_bounds__(512) k_hyst() {
    const int img = blockIdx.x;
    const int r = threadIdx.x;
    __shared__ unsigned int hd[512 * HD_STRIDE];   // ~34.8 KB, conflict-free stride
    __shared__ int cnt[2];

    unsigned int Wk[16], E[16], Hh[16];
    const uint4* wp = reinterpret_cast<const uint4*>(g_weak   + (size_t)img * H * WORDS + r * WORDS);
    const uint4* sp = reinterpret_cast<const uint4*>(g_strong + (size_t)img * H * WORDS + r * WORDS);
    #pragma unroll
    for (int q = 0; q < 4; q++) {
        uint4 v = wp[q]; Wk[4*q]=v.x; Wk[4*q+1]=v.y; Wk[4*q+2]=v.z; Wk[4*q+3]=v.w;
        uint4 u = sp[q]; E [4*q]=u.x; E [4*q+1]=u.y; E [4*q+2]=u.z; E [4*q+3]=u.w;
    }
    if (r == 0) { cnt[0] = 0; cnt[1] = 0; }

    for (int it = 0; it < 16; it++) {
        #pragma unroll
        for (int k = 0; k < 16; k++) {
            unsigned int l  = k        ? E[k-1] : 0u;
            unsigned int rt = (k < 15) ? E[k+1] : 0u;
            Hh[k] = E[k] | (E[k] << 1) | (E[k] >> 1) | (l >> 31) | (rt << 31);
            hd[r * HD_STRIDE + k] = Hh[k];
        }
        __syncthreads();
        #pragma unroll
        for (int k = 0; k < 16; k++) {
            unsigned int up = r         ? hd[(r-1) * HD_STRIDE + k] : 0u;
            unsigned int dn = (r < 511) ? hd[(r+1) * HD_STRIDE + k] : 0u;
            E[k] = Wk[k] & (Hh[k] | up | dn);
        }
        __syncthreads();
    }

    int ec = 0;
    #pragma unroll
    for (int k = 0; k < 16; k++) ec += __popc(E[k]);

    // final full dilation (no weak mask) for continuity numerator
    #pragma unroll
    for (int k = 0; k < 16; k++) {
        unsigned int l  = k        ? E[k-1] : 0u;
        unsigned int rt = (k < 15) ? E[k+1] : 0u;
        Hh[k] = E[k] | (E[k] << 1) | (E[k] >> 1) | (l >> 31) | (rt << 31);
        hd[r * HD_STRIDE + k] = Hh[k];
    }
    __syncthreads();
    int dc = 0;
    #pragma unroll
    for (int k = 0; k < 16; k++) {
        unsigned int up = r         ? hd[(r-1) * HD_STRIDE + k] : 0u;
        unsigned int dn = (r < 511) ? hd[(r+1) * HD_STRIDE + k] : 0u;
        dc += __popc(Hh[k] | up | dn);
    }

    #pragma unroll
    for (int off = 16; off; off >>= 1) {
        ec += __shfl_down_sync(0xffffffffu, ec, off);
        dc += __shfl_down_sync(0xffffffffu, dc, off);
    }
    if ((r & 31) == 0) { atomicAdd(&cnt[0], ec); atomicAdd(&cnt[1], dc); }
    __syncthreads();
    if (r == 0) {
        g_counts[img * 2 + 0] = (unsigned)cnt[0];
        g_counts[img * 2 + 1] = (unsigned)cnt[1];
    }
}

// ---------------- kernel 4: feature assembly + MLP -------------------------------
__global__ void __launch_bounds__(64) k_mlp(const float* __restrict__ W1,
                                            const float* __restrict__ b1,
                                            const float* __restrict__ W2,
                                            const float* __restrict__ b2,
                                            float* __restrict__ out) {
    int img = threadIdx.x;
    const double inv = 1.0 / (double)HW;
    double ssum = g_stats[img*8+0];
    double asum = g_stats[img*8+1];
    double a2   = g_stats[img*8+2];
    double lsum = g_stats[img*8+3];
    double l2   = g_stats[img*8+4];
    unsigned ec = g_counts[img*2+0], dc = g_counts[img*2+1];

    float f0 = (float)ec / (float)HW;                       // edge_density (exact)
    float f1 = (float)(ssum * inv / 255.0);                 // mean_edge_strength
    float f2 = (float)dc / ((float)ec + 1e-10f);            // continuity
    double am = asum * inv;
    float f3 = (float)(a2 * inv - am * am);                 // angle_var
    double lm = lsum * inv;
    float f4 = (float)((l2 * inv - lm * lm) / 1000.0);      // high_freq

    float feat[5] = {f0, f1, f2, f3, f4};
    float h[32];
    #pragma unroll
    for (int j = 0; j < 32; j++) {
        float acc = b1[j];
        #pragma unroll
        for (int f = 0; f < 5; f++) acc += feat[f] * W1[f * 32 + j];
        h[j] = fmaxf(acc, 0.0f);
    }
    for (int k = 0; k < 64; k++) {
        float acc = b2[k];
        #pragma unroll
        for (int j = 0; j < 32; j++) acc += h[j] * W2[j * 64 + k];
        out[img * 64 + k] = fmaxf(acc, 0.0f);
    }
}

// ---------------- launch ---------------------------------------------------------
extern "C" void kernel_launch(void* const* d_in, const int* in_sizes, int n_in,
                              void* d_out, int out_size) {
    const float* x  = (const float*)d_in[0];
    const float* W1 = (const float*)d_in[1];
    const float* b1 = (const float*)d_in[2];
    const float* W2 = (const float*)d_in[3];
    const float* b2 = (const float*)d_in[4];
    float* out = (float*)d_out;

    int blocks = (IMGS * HW / 4 + 255) / 256;     // 16384
    k_gray<<<blocks, 256>>>(x);
    dim3 g2(16, 16, IMGS), t2(32, 8);
    k_sobel<<<g2, t2>>>();
    k_hyst<<<IMGS, 512>>>();
    k_mlp<<<1, 64>>>(W1, b1, W2, b2, out);
}

// round 4
// speedup vs baseline: 1.2189x; 1.2189x over previous
#include <cuda_runtime.h>
#include <math.h>

#define IMGS 64
#define H 512
#define W 512
#define HW (H*W)
#define WORDS 16          // 512 bits / 32 per row
#define HD_STRIDE 17      // padded stride (words) to avoid smem bank conflicts

// ---------------- scratch (static device globals; no allocation) ----------------
__device__ unsigned int  g_weak[(size_t)IMGS * H * WORDS];   // 2 MB
__device__ unsigned int  g_strong[(size_t)IMGS * H * WORDS]; // 2 MB
__device__ double        g_part[(size_t)IMGS * 256 * 5];     // per-block stat partials

// ---------------- exact grayscale (matches jnp.round semantics bitwise) ---------
__device__ __forceinline__ float gray_of(float r, float g, float b) {
    // u8 = rint(clip(x,0,1)*255); gray = rint(0.299 r + 0.587 g + 0.114 b)
    // explicit round-to-nearest ops prevent FMA contraction (bitwise match)
    float R  = rintf(__fmul_rn(__saturatef(r), 255.0f));
    float G  = rintf(__fmul_rn(__saturatef(g), 255.0f));
    float Bv = rintf(__fmul_rn(__saturatef(b), 255.0f));
    float y  = __fadd_rn(__fadd_rn(__fmul_rn(0.299f, R), __fmul_rn(0.587f, G)),
                         __fmul_rn(0.114f, Bv));
    return rintf(y);
}

// ---------------- kernel 1: fused gray + Sobel / NMS / stat partials ------------
// One block = 32x32 output tile; block (32,8), 4 rows per thread.
__global__ void __launch_bounds__(256) k_sobel(const float* __restrict__ x) {
    const int bx = blockIdx.x, by = blockIdx.y, img = blockIdx.z;
    const int x0 = bx * 32, y0 = by * 32;
    const int tx = threadIdx.x;
    const int tid = threadIdx.y * 32 + tx;

    __shared__ float sg[36][37];    // gray with halo 2 (reflect-101 applied)
    __shared__ float smag[34][35];  // |gx|+|gy| with halo 1 (0 outside image)
    __shared__ double red[8][5];

    const float* base = x + (size_t)img * 3 * HW;

    // gray halo: compute gray directly from x (no intermediate global buffer)
    for (int t = tid; t < 36 * 36; t += 256) {
        int ly = t / 36, lx = t % 36;
        int iy = y0 - 2 + ly, ix = x0 - 2 + lx;
        iy = iy < 0 ? -iy : (iy > 511 ? 1022 - iy : iy);   // BORDER_REFLECT_101
        ix = ix < 0 ? -ix : (ix > 511 ? 1022 - ix : ix);
        int p = iy * 512 + ix;
        sg[ly][lx] = gray_of(base[p], base[HW + p], base[2 * HW + p]);
    }
    __syncthreads();

    // mag halo (zero-padded outside image, matching the reference's _shift)
    for (int t = tid; t < 34 * 34; t += 256) {
        int my = t / 34, mx = t % 34;
        int iy = y0 - 1 + my, ix = x0 - 1 + mx;
        int ly = my + 1, lx = mx + 1;
        float a = sg[ly-1][lx-1], b = sg[ly-1][lx], c = sg[ly-1][lx+1];
        float d = sg[ly  ][lx-1],                   e = sg[ly  ][lx+1];
        float f = sg[ly+1][lx-1], g = sg[ly+1][lx], h = sg[ly+1][lx+1];
        float gx = (c - a) + 2.0f * (e - d) + (h - f);           // SOBEL_X corr
        float gy = (f + 2.0f * g + h) - (a + 2.0f * b + c);      // SOBEL_Y corr
        bool inside = (iy >= 0) & (iy < 512) & (ix >= 0) & (ix < 512);
        smag[my][mx] = inside ? (fabsf(gx) + fabsf(gy)) : 0.0f;
    }
    __syncthreads();

    float s_str = 0.f, s_ang = 0.f, s_ang2 = 0.f, s_lap = 0.f, s_lap2 = 0.f;

    #pragma unroll
    for (int rr = 0; rr < 4; rr++) {
        int ty = threadIdx.y + rr * 8;
        int ly = ty + 2, lx = tx + 2;
        int my = ty + 1, mx = tx + 1;
        // recompute gx,gy for own pixel (identical expression -> identical bits)
        float a = sg[ly-1][lx-1], b = sg[ly-1][lx], c = sg[ly-1][lx+1];
        float d = sg[ly  ][lx-1],                   e = sg[ly  ][lx+1];
        float f = sg[ly+1][lx-1], g = sg[ly+1][lx], h = sg[ly+1][lx+1];
        float gx = (c - a) + 2.0f * (e - d) + (h - f);
        float gy = (f + 2.0f * g + h) - (a + 2.0f * b + c);
        float mag = smag[my][mx];
        float ang = atan2f(gy, gx);
        float str = sqrtf(gx * gx + gy * gy);
        float lap = b + g + d + e - 4.0f * sg[ly][lx];
        s_str += str; s_ang += ang; s_ang2 += ang * ang;
        s_lap += lap; s_lap2 += lap * lap;

        float adeg = ang * 57.29577951308232f;   // (float)(180/pi), as JAX
        if (adeg < 0.0f) adeg += 180.0f;         // jnp.mod(.,180) for (-180,180]
        float n1, n2;
        if (adeg < 22.5f || adeg >= 157.5f) { n1 = smag[my][mx+1];   n2 = smag[my][mx-1]; }
        else if (adeg < 67.5f)              { n1 = smag[my-1][mx+1]; n2 = smag[my+1][mx-1]; }
        else if (adeg < 112.5f)             { n1 = smag[my-1][mx];   n2 = smag[my+1][mx]; }
        else                                { n1 = smag[my-1][mx-1]; n2 = smag[my+1][mx+1]; }
        bool pass = (mag >= n1) && (mag >= n2);   // exact integer comparisons

        unsigned wb = __ballot_sync(0xffffffffu, pass && (mag >= 50.0f));
        unsigned sb = __ballot_sync(0xffffffffu, pass && (mag >= 150.0f));
        if (tx == 0) {
            int iy = y0 + ty;
            g_weak  [(size_t)img * H * WORDS + iy * WORDS + bx] = wb;
            g_strong[(size_t)img * H * WORDS + iy * WORDS + bx] = sb;
        }
    }

    // block reduction of 5 stats (double) -> deterministic partial write (no atomics)
    double d0 = s_str, d1 = s_ang, d2 = s_ang2, d3 = s_lap, d4 = s_lap2;
    #pragma unroll
    for (int off = 16; off; off >>= 1) {
        d0 += __shfl_down_sync(0xffffffffu, d0, off);
        d1 += __shfl_down_sync(0xffffffffu, d1, off);
        d2 += __shfl_down_sync(0xffffffffu, d2, off);
        d3 += __shfl_down_sync(0xffffffffu, d3, off);
        d4 += __shfl_down_sync(0xffffffffu, d4, off);
    }
    if (tx == 0) {
        red[threadIdx.y][0] = d0; red[threadIdx.y][1] = d1; red[threadIdx.y][2] = d2;
        red[threadIdx.y][3] = d3; red[threadIdx.y][4] = d4;
    }
    __syncthreads();
    if (tid < 5) {
        double s = 0.0;
        #pragma unroll
        for (int wi = 0; wi < 8; wi++) s += red[wi][tid];
        g_part[((size_t)img * 256 + by * 16 + bx) * 5 + tid] = s;
    }
}

// ---------------- kernel 2: hysteresis + stat reduce + feature MLP --------------
// One CTA per image; thread r owns row r of the bitmaps.
__global__ void __launch_bounds__(512) k_hyst(const float* __restrict__ W1,
                                              const float* __restrict__ b1,
                                              const float* __restrict__ W2,
                                              const float* __restrict__ b2,
                                              float* __restrict__ out) {
    const int img = blockIdx.x;
    const int r = threadIdx.x;
    __shared__ unsigned int hd[512 * HD_STRIDE];   // ~34.8 KB, conflict-free
    __shared__ int cnt[2];
    __shared__ double sred[8][5];
    __shared__ double sstat[5];
    __shared__ float sh[32];
    __shared__ float sfeat[5];

    unsigned int Wk[16], E[16], Hh[16];
    const uint4* wp = reinterpret_cast<const uint4*>(g_weak   + (size_t)img * H * WORDS + r * WORDS);
    const uint4* sp = reinterpret_cast<const uint4*>(g_strong + (size_t)img * H * WORDS + r * WORDS);
    #pragma unroll
    for (int q = 0; q < 4; q++) {
        uint4 v = wp[q]; Wk[4*q]=v.x; Wk[4*q+1]=v.y; Wk[4*q+2]=v.z; Wk[4*q+3]=v.w;
        uint4 u = sp[q]; E [4*q]=u.x; E [4*q+1]=u.y; E [4*q+2]=u.z; E [4*q+3]=u.w;
    }
    if (r == 0) { cnt[0] = 0; cnt[1] = 0; }

    // stat partial reduction (threads 0..255 own one partial each)
    double p0 = 0, p1 = 0, p2 = 0, p3 = 0, p4 = 0;
    if (r < 256) {
        const double* pp = g_part + ((size_t)img * 256 + r) * 5;
        p0 = pp[0]; p1 = pp[1]; p2 = pp[2]; p3 = pp[3]; p4 = pp[4];
    }
    #pragma unroll
    for (int off = 16; off; off >>= 1) {
        p0 += __shfl_down_sync(0xffffffffu, p0, off);
        p1 += __shfl_down_sync(0xffffffffu, p1, off);
        p2 += __shfl_down_sync(0xffffffffu, p2, off);
        p3 += __shfl_down_sync(0xffffffffu, p3, off);
        p4 += __shfl_down_sync(0xffffffffu, p4, off);
    }
    if ((r & 31) == 0 && r < 256) {
        int wi = r >> 5;
        sred[wi][0] = p0; sred[wi][1] = p1; sred[wi][2] = p2;
        sred[wi][3] = p3; sred[wi][4] = p4;
    }

    // 16 Jacobi hysteresis iterations (bitwise; matches fori_loop semantics)
    for (int it = 0; it < 16; it++) {
        #pragma unroll
        for (int k = 0; k < 16; k++) {
            unsigned int l  = k        ? E[k-1] : 0u;
            unsigned int rt = (k < 15) ? E[k+1] : 0u;
            Hh[k] = E[k] | (E[k] << 1) | (E[k] >> 1) | (l >> 31) | (rt << 31);
            hd[r * HD_STRIDE + k] = Hh[k];
        }
        __syncthreads();
        #pragma unroll
        for (int k = 0; k < 16; k++) {
            unsigned int up = r         ? hd[(r-1) * HD_STRIDE + k] : 0u;
            unsigned int dn = (r < 511) ? hd[(r+1) * HD_STRIDE + k] : 0u;
            E[k] = Wk[k] & (Hh[k] | up | dn);
        }
        __syncthreads();
    }

    int ec = 0;
    #pragma unroll
    for (int k = 0; k < 16; k++) ec += __popc(E[k]);

    // final full dilation (no weak mask) for continuity numerator
    #pragma unroll
    for (int k = 0; k < 16; k++) {
        unsigned int l  = k        ? E[k-1] : 0u;
        unsigned int rt = (k < 15) ? E[k+1] : 0u;
        Hh[k] = E[k] | (E[k] << 1) | (E[k] >> 1) | (l >> 31) | (rt << 31);
        hd[r * HD_STRIDE + k] = Hh[k];
    }
    __syncthreads();
    int dc = 0;
    #pragma unroll
    for (int k = 0; k < 16; k++) {
        unsigned int up = r         ? hd[(r-1) * HD_STRIDE + k] : 0u;
        unsigned int dn = (r < 511) ? hd[(r+1) * HD_STRIDE + k] : 0u;
        dc += __popc(Hh[k] | up | dn);
    }

    #pragma unroll
    for (int off = 16; off; off >>= 1) {
        ec += __shfl_down_sync(0xffffffffu, ec, off);
        dc += __shfl_down_sync(0xffffffffu, dc, off);
    }
    if ((r & 31) == 0) { atomicAdd(&cnt[0], ec); atomicAdd(&cnt[1], dc); }
    __syncthreads();

    // ---- features + MLP (per-image, inside this block) ----
    if (r == 0) {
        double s0 = 0, s1 = 0, s2 = 0, s3 = 0, s4 = 0;
        #pragma unroll
        for (int wi = 0; wi < 8; wi++) {
            s0 += sred[wi][0]; s1 += sred[wi][1]; s2 += sred[wi][2];
            s3 += sred[wi][3]; s4 += sred[wi][4];
        }
        sstat[0] = s0; sstat[1] = s1; sstat[2] = s2; sstat[3] = s3; sstat[4] = s4;

        const double inv = 1.0 / (double)HW;
        unsigned uec = (unsigned)cnt[0], udc = (unsigned)cnt[1];
        sfeat[0] = (float)uec / (float)HW;                    // edge_density
        sfeat[1] = (float)(s0 * inv / 255.0);                 // mean_edge_strength
        sfeat[2] = (float)udc / ((float)uec + 1e-10f);        // continuity
        double am = s1 * inv;
        sfeat[3] = (float)(s2 * inv - am * am);               // angle_var
        double lm = s3 * inv;
        sfeat[4] = (float)((s4 * inv - lm * lm) / 1000.0);    // high_freq
    }
    __syncthreads();

    if (r < 32) {
        float acc = b1[r];
        #pragma unroll
        for (int f = 0; f < 5; f++) acc += sfeat[f] * W1[f * 32 + r];
        sh[r] = fmaxf(acc, 0.0f);
    }
    __syncthreads();
    if (r < 64) {
        float acc = b2[r];
        #pragma unroll
        for (int j = 0; j < 32; j++) acc += sh[j] * W2[j * 64 + r];
        out[img * 64 + r] = fmaxf(acc, 0.0f);
    }
}

// ---------------- launch ---------------------------------------------------------
extern "C" void kernel_launch(void* const* d_in, const int* in_sizes, int n_in,
                              void* d_out, int out_size) {
    const float* x  = (const float*)d_in[0];
    const float* W1 = (const float*)d_in[1];
    const float* b1 = (const float*)d_in[2];
    const float* W2 = (const float*)d_in[3];
    const float* b2 = (const float*)d_in[4];
    float* out = (float*)d_out;

    dim3 g2(16, 16, IMGS), t2(32, 8);
    k_sobel<<<g2, t2>>>(x);
    k_hyst<<<IMGS, 512>>>(W1, b1, W2, b2, out);
}

// round 5
// speedup vs baseline: 1.4070x; 1.1543x over previous
#include <cuda_runtime.h>
#include <math.h>

#define IMGS 64
#define H 512
#define W 512
#define HW (H*W)
#define WORDS 16          // 512 bits / 32 per row
#define HD_STRIDE 17      // padded stride (words) to avoid smem bank conflicts

// ---------------- scratch (static device globals; no allocation) ----------------
__device__ unsigned int  g_weak[(size_t)IMGS * H * WORDS];   // 2 MB
__device__ unsigned int  g_strong[(size_t)IMGS * H * WORDS]; // 2 MB
__device__ double        g_part[(size_t)IMGS * 256 * 5];     // per-block stat partials

// ---------------- exact grayscale (matches jnp.round semantics bitwise) ---------
__device__ __forceinline__ float gray_of(float r, float g, float b) {
    float R  = rintf(__fmul_rn(__saturatef(r), 255.0f));
    float G  = rintf(__fmul_rn(__saturatef(g), 255.0f));
    float Bv = rintf(__fmul_rn(__saturatef(b), 255.0f));
    float y  = __fadd_rn(__fadd_rn(__fmul_rn(0.299f, R), __fmul_rn(0.587f, G)),
                         __fmul_rn(0.114f, Bv));
    return rintf(y);
}

__device__ __forceinline__ float sqrt_fast(float x) {
    float r; asm("sqrt.approx.f32 %0, %1;" : "=f"(r) : "f"(x)); return r;
}

// fast atan2 for STATS ONLY (~5e-7 rad abs err; Cephes atanf poly)
__device__ __forceinline__ float atan2_fast(float gy, float gx) {
    float ax = fabsf(gx), ay = fabsf(gy);
    float mn = fminf(ax, ay), mx = fmaxf(ax, ay);
    float t = (mx > 0.0f) ? __fdividef(mn, mx) : 0.0f;   // [0,1]
    bool redu = t > 0.4142135623730950f;
    float u = redu ? __fdividef(t - 1.0f, t + 1.0f) : t;
    float z = u * u;
    float p = fmaf(fmaf(fmaf(8.05374449538e-2f, z, -1.38776856032e-1f), z,
                        1.99777106478e-1f), z, -3.33329491539e-1f);
    float r = fmaf(p * z, u, u);
    if (redu) r += 0.7853981633974483f;
    float th = (ay > ax) ? (1.5707963267948966f - r) : r;
    if (gx < 0.0f) th = 3.14159265358979f - th;
    return copysignf(th, gy);
}

// ---------------- kernel 1: fused gray + Sobel / NMS / stat partials ------------
// One block = 32x32 output tile; block (32,8); thread owns 4 ADJACENT rows
// (sliding 3x3 window in registers).
__global__ void __launch_bounds__(256) k_sobel(const float* __restrict__ x) {
    const int bx = blockIdx.x, by = blockIdx.y, img = blockIdx.z;
    const int x0 = bx * 32, y0 = by * 32;
    const int tx = threadIdx.x;
    const int tid = threadIdx.y * 32 + tx;

    __shared__ float sg[36][37];    // gray with halo 2 (reflect-101)
    __shared__ float smag[34][35];  // |gx|+|gy| with halo 1 (0 outside image)
    __shared__ double red[8][5];

    const float* base = x + (size_t)img * 3 * HW;

    for (int t = tid; t < 36 * 36; t += 256) {
        int ly = t / 36, lx = t % 36;
        int iy = y0 - 2 + ly, ix = x0 - 2 + lx;
        iy = iy < 0 ? -iy : (iy > 511 ? 1022 - iy : iy);   // BORDER_REFLECT_101
        ix = ix < 0 ? -ix : (ix > 511 ? 1022 - ix : ix);
        int p = iy * 512 + ix;
        sg[ly][lx] = gray_of(base[p], base[HW + p], base[2 * HW + p]);
    }
    __syncthreads();

    // mag halo (all integer-valued floats -> exact in any association)
    for (int t = tid; t < 34 * 34; t += 256) {
        int my = t / 34, mx = t % 34;
        int iy = y0 - 1 + my, ix = x0 - 1 + mx;
        int ly = my + 1, lx = mx + 1;
        float a = sg[ly-1][lx-1], b = sg[ly-1][lx], c = sg[ly-1][lx+1];
        float d = sg[ly  ][lx-1],                   e = sg[ly  ][lx+1];
        float f = sg[ly+1][lx-1], g = sg[ly+1][lx], h = sg[ly+1][lx+1];
        float gx = (c - a) + 2.0f * (e - d) + (h - f);
        float gy = (f + 2.0f * g + h) - (a + 2.0f * b + c);
        bool inside = (iy >= 0) & (iy < 512) & (ix >= 0) & (ix < 512);
        smag[my][mx] = inside ? (fabsf(gx) + fabsf(gy)) : 0.0f;  // zero-pad shift
    }
    __syncthreads();

    float s_str = 0.f, s_ang = 0.f, s_ang2 = 0.f, s_lap = 0.f, s_lap2 = 0.f;

    const int ty0 = threadIdx.y * 4;          // 4 adjacent rows per thread
    // sliding window over sg rows ty+1..ty+3, cols tx+1..tx+3
    float u0 = sg[ty0+1][tx+1], u1 = sg[ty0+1][tx+2], u2 = sg[ty0+1][tx+3];
    float m0 = sg[ty0+2][tx+1], m1 = sg[ty0+2][tx+2], m2 = sg[ty0+2][tx+3];

    #pragma unroll
    for (int rr = 0; rr < 4; rr++) {
        const int ty = ty0 + rr;
        float d0v = sg[ty+3][tx+1], d1v = sg[ty+3][tx+2], d2v = sg[ty+3][tx+3];
        float gx = (u2 - u0) + 2.0f * (m2 - m0) + (d2v - d0v);
        float gy = (d0v + 2.0f * d1v + d2v) - (u0 + 2.0f * u1 + u2);
        float lap = u1 + d1v + m0 + m2 - 4.0f * m1;
        float mag = fabsf(gx) + fabsf(gy);          // == smag value (exact ints)

        float ang = atan2_fast(gy, gx);
        float str = sqrt_fast(gx * gx + gy * gy);
        s_str += str; s_ang += ang; s_ang2 += ang * ang;
        s_lap += lap; s_lap2 += lap * lap;

        // sector from exact gradient comparisons (tan 22.5 / tan 67.5)
        float ax = fabsf(gx), ay = fabsf(gy);
        bool sd0  = (ay < 0.41421356237f * ax) || (ax == 0.0f && ay == 0.0f);
        bool sd90 = !sd0 && (ay > 2.41421356237f * ax);
        bool band = !sd0 && !sd90;
        bool same = (gx > 0.0f) == (gy > 0.0f);     // both nonzero in band
        bool sd45 = band && same;
        int dy = sd0 ? 0 : -1;
        int dx = (sd0 || sd45) ? 1 : (sd90 ? 0 : -1);

        const int my = ty + 1, mx = tx + 1;
        float n1 = smag[my + dy][mx + dx];
        float n2 = smag[my - dy][mx - dx];
        bool pass = (mag >= n1) && (mag >= n2);     // exact integer comparisons

        unsigned wb = __ballot_sync(0xffffffffu, pass && (mag >= 50.0f));
        unsigned sb = __ballot_sync(0xffffffffu, pass && (mag >= 150.0f));
        if (tx == 0) {
            int iy = y0 + ty;
            g_weak  [(size_t)img * H * WORDS + iy * WORDS + bx] = wb;
            g_strong[(size_t)img * H * WORDS + iy * WORDS + bx] = sb;
        }
        // slide window down one row
        u0 = m0; u1 = m1; u2 = m2;
        m0 = d0v; m1 = d1v; m2 = d2v;
    }

    // block reduction (double) -> deterministic per-block partial (no atomics)
    double d0 = s_str, d1 = s_ang, d2 = s_ang2, d3 = s_lap, d4 = s_lap2;
    #pragma unroll
    for (int off = 16; off; off >>= 1) {
        d0 += __shfl_down_sync(0xffffffffu, d0, off);
        d1 += __shfl_down_sync(0xffffffffu, d1, off);
        d2 += __shfl_down_sync(0xffffffffu, d2, off);
        d3 += __shfl_down_sync(0xffffffffu, d3, off);
        d4 += __shfl_down_sync(0xffffffffu, d4, off);
    }
    if (tx == 0) {
        red[threadIdx.y][0] = d0; red[threadIdx.y][1] = d1; red[threadIdx.y][2] = d2;
        red[threadIdx.y][3] = d3; red[threadIdx.y][4] = d4;
    }
    __syncthreads();
    if (tid < 5) {
        double s = 0.0;
        #pragma unroll
        for (int wi = 0; wi < 8; wi++) s += red[wi][tid];
        g_part[((size_t)img * 256 + by * 16 + bx) * 5 + tid] = s;
    }
}

// ---------------- kernel 2: hysteresis + stat reduce + feature MLP --------------
__global__ void __launch_bounds__(512) k_hyst(const float* __restrict__ W1,
                                              const float* __restrict__ b1,
                                              const float* __restrict__ W2,
                                              const float* __restrict__ b2,
                                              float* __restrict__ out) {
    const int img = blockIdx.x;
    const int r = threadIdx.x;
    __shared__ unsigned int hd[512 * HD_STRIDE];
    __shared__ int cnt[2];
    __shared__ double sred[8][5];
    __shared__ float sh[32];
    __shared__ float sfeat[5];

    unsigned int Wk[16], E[16], Hh[16];
    const uint4* wp = reinterpret_cast<const uint4*>(g_weak   + (size_t)img * H * WORDS + r * WORDS);
    const uint4* sp = reinterpret_cast<const uint4*>(g_strong + (size_t)img * H * WORDS + r * WORDS);
    #pragma unroll
    for (int q = 0; q < 4; q++) {
        uint4 v = wp[q]; Wk[4*q]=v.x; Wk[4*q+1]=v.y; Wk[4*q+2]=v.z; Wk[4*q+3]=v.w;
        uint4 u = sp[q]; E [4*q]=u.x; E [4*q+1]=u.y; E [4*q+2]=u.z; E [4*q+3]=u.w;
    }
    if (r == 0) { cnt[0] = 0; cnt[1] = 0; }

    // stat partial reduction (threads 0..255)
    double p0 = 0, p1 = 0, p2 = 0, p3 = 0, p4 = 0;
    if (r < 256) {
        const double* pp = g_part + ((size_t)img * 256 + r) * 5;
        p0 = pp[0]; p1 = pp[1]; p2 = pp[2]; p3 = pp[3]; p4 = pp[4];
    }
    #pragma unroll
    for (int off = 16; off; off >>= 1) {
        p0 += __shfl_down_sync(0xffffffffu, p0, off);
        p1 += __shfl_down_sync(0xffffffffu, p1, off);
        p2 += __shfl_down_sync(0xffffffffu, p2, off);
        p3 += __shfl_down_sync(0xffffffffu, p3, off);
        p4 += __shfl_down_sync(0xffffffffu, p4, off);
    }
    if ((r & 31) == 0 && r < 256) {
        int wi = r >> 5;
        sred[wi][0] = p0; sred[wi][1] = p1; sred[wi][2] = p2;
        sred[wi][3] = p3; sred[wi][4] = p4;
    }

    // Jacobi hysteresis with fixed-point early exit (bitwise-identical result:
    // once E stops changing, remaining iterations are identity)
    for (int it = 0; it < 16; it++) {
        #pragma unroll
        for (int k = 0; k < 16; k++) {
            unsigned int l  = k        ? E[k-1] : 0u;
            unsigned int rt = (k < 15) ? E[k+1] : 0u;
            Hh[k] = E[k] | (E[k] << 1) | (E[k] >> 1) | (l >> 31) | (rt << 31);
            hd[r * HD_STRIDE + k] = Hh[k];
        }
        __syncthreads();
        unsigned int chg = 0;
        #pragma unroll
        for (int k = 0; k < 16; k++) {
            unsigned int up = r         ? hd[(r-1) * HD_STRIDE + k] : 0u;
            unsigned int dn = (r < 511) ? hd[(r+1) * HD_STRIDE + k] : 0u;
            unsigned int ne = Wk[k] & (Hh[k] | up | dn);
            chg |= ne ^ E[k];
            E[k] = ne;
        }
        if (!__syncthreads_or((int)(chg != 0u))) break;   // barrier + convergence
    }

    int ec = 0;
    #pragma unroll
    for (int k = 0; k < 16; k++) ec += __popc(E[k]);

    // final full dilation (no weak mask) for continuity numerator
    #pragma unroll
    for (int k = 0; k < 16; k++) {
        unsigned int l  = k        ? E[k-1] : 0u;
        unsigned int rt = (k < 15) ? E[k+1] : 0u;
        Hh[k] = E[k] | (E[k] << 1) | (E[k] >> 1) | (l >> 31) | (rt << 31);
        hd[r * HD_STRIDE + k] = Hh[k];
    }
    __syncthreads();
    int dc = 0;
    #pragma unroll
    for (int k = 0; k < 16; k++) {
        unsigned int up = r         ? hd[(r-1) * HD_STRIDE + k] : 0u;
        unsigned int dn = (r < 511) ? hd[(r+1) * HD_STRIDE + k] : 0u;
        dc += __popc(Hh[k] | up | dn);
    }

    #pragma unroll
    for (int off = 16; off; off >>= 1) {
        ec += __shfl_down_sync(0xffffffffu, ec, off);
        dc += __shfl_down_sync(0xffffffffu, dc, off);
    }
    if ((r & 31) == 0) { atomicAdd(&cnt[0], ec); atomicAdd(&cnt[1], dc); }
    __syncthreads();

    // ---- features + MLP ----
    if (r == 0) {
        double s0 = 0, s1 = 0, s2 = 0, s3 = 0, s4 = 0;
        #pragma unroll
        for (int wi = 0; wi < 8; wi++) {
            s0 += sred[wi][0]; s1 += sred[wi][1]; s2 += sred[wi][2];
            s3 += sred[wi][3]; s4 += sred[wi][4];
        }
        const double inv = 1.0 / (double)HW;
        unsigned uec = (unsigned)cnt[0], udc = (unsigned)cnt[1];
        sfeat[0] = (float)uec / (float)HW;                    // edge_density
        sfeat[1] = (float)(s0 * inv / 255.0);                 // mean_edge_strength
        sfeat[2] = (float)udc / ((float)uec + 1e-10f);        // continuity
        double am = s1 * inv;
        sfeat[3] = (float)(s2 * inv - am * am);               // angle_var
        double lm = s3 * inv;
        sfeat[4] = (float)((s4 * inv - lm * lm) / 1000.0);    // high_freq
    }
    __syncthreads();

    if (r < 32) {
        float acc = b1[r];
        #pragma unroll
        for (int f = 0; f < 5; f++) acc += sfeat[f] * W1[f * 32 + r];
        sh[r] = fmaxf(acc, 0.0f);
    }
    __syncthreads();
    if (r < 64) {
        float acc = b2[r];
        #pragma unroll
        for (int j = 0; j < 32; j++) acc += sh[j] * W2[j * 64 + r];
        out[img * 64 + r] = fmaxf(acc, 0.0f);
    }
}

// ---------------- launch ---------------------------------------------------------
extern "C" void kernel_launch(void* const* d_in, const int* in_sizes, int n_in,
                              void* d_out, int out_size) {
    const float* x  = (const float*)d_in[0];
    const float* W1 = (const float*)d_in[1];
    const float* b1 = (const float*)d_in[2];
    const float* W2 = (const float*)d_in[3];
    const float* b2 = (const float*)d_in[4];
    float* out = (float*)d_out;

    dim3 g2(16, 16, IMGS), t2(32, 8);
    k_sobel<<<g2, t2>>>(x);
    k_hyst<<<IMGS, 512>>>(W1, b1, W2, b2, out);
}

// round 6
// speedup vs baseline: 1.4684x; 1.0437x over previous
#include <cuda_runtime.h>
#include <math.h>

#define IMGS 64
#define H 512
#define W 512
#define HW (H*W)
#define WORDS 16          // 512 bits / 32 per row
#define HD_STRIDE 17      // padded stride (words) to avoid smem bank conflicts
#define HY_ROWS 280       // rows per hysteresis CTA (256 core + 24 halo)
#define HY_THREADS 288

// ---------------- scratch (static device globals; no allocation) ----------------
__device__ unsigned int  g_weak[(size_t)IMGS * H * WORDS];   // 2 MB
__device__ unsigned int  g_strong[(size_t)IMGS * H * WORDS]; // 2 MB
__device__ double        g_part[(size_t)IMGS * 256 * 5];     // per-block stat partials
__device__ unsigned int  g_cnt[IMGS * 2];                    // edge / dil counts
__device__ int           g_sync[IMGS];                       // per-image CTA ticket

// ---------------- exact grayscale (matches jnp.round semantics bitwise) ---------
__device__ __forceinline__ float gray_of(float r, float g, float b) {
    float R  = rintf(__fmul_rn(__saturatef(r), 255.0f));
    float G  = rintf(__fmul_rn(__saturatef(g), 255.0f));
    float Bv = rintf(__fmul_rn(__saturatef(b), 255.0f));
    float y  = __fadd_rn(__fadd_rn(__fmul_rn(0.299f, R), __fmul_rn(0.587f, G)),
                         __fmul_rn(0.114f, Bv));
    return rintf(y);
}

__device__ __forceinline__ float sqrt_fast(float x) {
    float r; asm("sqrt.approx.f32 %0, %1;" : "=f"(r) : "f"(x)); return r;
}

// fast atan2 for STATS ONLY (~5e-7 rad abs err)
__device__ __forceinline__ float atan2_fast(float gy, float gx) {
    float ax = fabsf(gx), ay = fabsf(gy);
    float mn = fminf(ax, ay), mx = fmaxf(ax, ay);
    float t = (mx > 0.0f) ? __fdividef(mn, mx) : 0.0f;
    bool redu = t > 0.4142135623730950f;
    float u = redu ? __fdividef(t - 1.0f, t + 1.0f) : t;
    float z = u * u;
    float p = fmaf(fmaf(fmaf(8.05374449538e-2f, z, -1.38776856032e-1f), z,
                        1.99777106478e-1f), z, -3.33329491539e-1f);
    float r = fmaf(p * z, u, u);
    if (redu) r += 0.7853981633974483f;
    float th = (ay > ax) ? (1.5707963267948966f - r) : r;
    if (gx < 0.0f) th = 3.14159265358979f - th;
    return copysignf(th, gy);
}

// ---------------- kernel 1: fused gray + Sobel / NMS / stat partials ------------
__global__ void __launch_bounds__(256, 5) k_sobel(const float* __restrict__ x) {
    const int bx = blockIdx.x, by = blockIdx.y, img = blockIdx.z;
    const int x0 = bx * 32, y0 = by * 32;
    const int tx = threadIdx.x;
    const int tid = threadIdx.y * 32 + tx;

    __shared__ float sg[36][37];    // gray with halo 2 (reflect-101)
    __shared__ float smag[34][35];  // |gx|+|gy| halo 1 (interior filled in pass A)
    __shared__ double red[8][5];

    if (bx == 0 && by == 0 && tid == 0) {   // reset sync state for this image
        g_sync[img] = 0; g_cnt[img*2] = 0; g_cnt[img*2+1] = 0;
    }

    const float* base = x + (size_t)img * 3 * HW;
    for (int t = tid; t < 36 * 36; t += 256) {
        int ly = t / 36, lx = t - ly * 36;
        int iy = y0 - 2 + ly, ix = x0 - 2 + lx;
        iy = iy < 0 ? -iy : (iy > 511 ? 1022 - iy : iy);   // BORDER_REFLECT_101
        ix = ix < 0 ? -ix : (ix > 511 ? 1022 - ix : ix);
        int p = iy * 512 + ix;
        sg[ly][lx] = gray_of(base[p], base[HW + p], base[2 * HW + p]);
    }
    __syncthreads();

    // smag RING only (132 px); interior written by pass A (disjoint cells)
    if (tid < 132) {
        int my, mx;
        if      (tid < 34)  { my = 0;               mx = tid; }
        else if (tid < 68)  { my = 33;              mx = tid - 34; }
        else if (tid < 100) { my = 1 + (tid - 68);  mx = 0; }
        else                { my = 1 + (tid - 100); mx = 33; }
        int iy = y0 - 1 + my, ix = x0 - 1 + mx;
        int ly = my + 1, lx = mx + 1;
        float a = sg[ly-1][lx-1], b = sg[ly-1][lx], c = sg[ly-1][lx+1];
        float d = sg[ly  ][lx-1],                   e = sg[ly  ][lx+1];
        float f = sg[ly+1][lx-1], g = sg[ly+1][lx], h = sg[ly+1][lx+1];
        float gx = (c - a) + 2.0f * (e - d) + (h - f);
        float gy = (f + 2.0f * g + h) - (a + 2.0f * b + c);
        bool inside = (iy >= 0) & (iy < 512) & (ix >= 0) & (ix < 512);
        smag[my][mx] = inside ? (fabsf(gx) + fabsf(gy)) : 0.0f;
    }

    // ---- pass A: gradients, stats, sector codes; fill smag interior ----
    float s_str = 0.f, s_ang = 0.f, s_ang2 = 0.f, s_lap = 0.f, s_lap2 = 0.f;
    const int ty0 = threadIdx.y * 4;
    float u0 = sg[ty0+1][tx+1], u1 = sg[ty0+1][tx+2], u2 = sg[ty0+1][tx+3];
    float m0 = sg[ty0+2][tx+1], m1 = sg[ty0+2][tx+2], m2 = sg[ty0+2][tx+3];
    float magv[4];
    unsigned codes = 0;

    #pragma unroll
    for (int rr = 0; rr < 4; rr++) {
        float d0v = sg[ty0+rr+3][tx+1], d1v = sg[ty0+rr+3][tx+2], d2v = sg[ty0+rr+3][tx+3];
        float gx = (u2 - u0) + 2.0f * (m2 - m0) + (d2v - d0v);   // integer-exact
        float gy = (d0v + 2.0f * d1v + d2v) - (u0 + 2.0f * u1 + u2);
        float lap = u1 + d1v + m0 + m2 - 4.0f * m1;
        float mag = fabsf(gx) + fabsf(gy);
        smag[ty0+rr+1][tx+1] = mag;
        magv[rr] = mag;

        float ang = atan2_fast(gy, gx);
        float str = sqrt_fast(gx * gx + gy * gy);
        s_str += str; s_ang += ang; s_ang2 += ang * ang;
        s_lap += lap; s_lap2 += lap * lap;

        float ax = fabsf(gx), ay = fabsf(gy);
        bool sd0  = (ay < 0.41421356237f * ax) || (ax == 0.0f && ay == 0.0f);
        bool sd90 = !sd0 && (ay > 2.41421356237f * ax);
        bool sd45 = !sd0 && !sd90 && ((gx > 0.0f) == (gy > 0.0f));
        unsigned code = sd0 ? 0u : (sd45 ? 1u : (sd90 ? 2u : 3u));
        codes |= code << (2 * rr);

        u0 = m0; u1 = m1; u2 = m2;
        m0 = d0v; m1 = d1v; m2 = d2v;
    }
    __syncthreads();

    // ---- pass B: NMS + thresholds + ballots ----
    #pragma unroll
    for (int rr = 0; rr < 4; rr++) {
        int my = ty0 + rr + 1, mx = tx + 1;
        unsigned code = (codes >> (2 * rr)) & 3u;
        int dy = (code == 0u) ? 0 : -1;
        int dx = (code <= 1u) ? 1 : (code == 2u ? 0 : -1);
        float n1 = smag[my + dy][mx + dx];
        float n2 = smag[my - dy][mx - dx];
        float mag = magv[rr];
        bool pass = (mag >= n1) && (mag >= n2);
        unsigned wb = __ballot_sync(0xffffffffu, pass && (mag >= 50.0f));
        unsigned sb = __ballot_sync(0xffffffffu, pass && (mag >= 150.0f));
        if (tx == 0) {
            int iy = y0 + ty0 + rr;
            g_weak  [(size_t)img * H * WORDS + iy * WORDS + bx] = wb;
            g_strong[(size_t)img * H * WORDS + iy * WORDS + bx] = sb;
        }
    }

    // block reduction -> deterministic per-block partial
    double d0 = s_str, d1 = s_ang, d2 = s_ang2, d3 = s_lap, d4 = s_lap2;
    #pragma unroll
    for (int off = 16; off; off >>= 1) {
        d0 += __shfl_down_sync(0xffffffffu, d0, off);
        d1 += __shfl_down_sync(0xffffffffu, d1, off);
        d2 += __shfl_down_sync(0xffffffffu, d2, off);
        d3 += __shfl_down_sync(0xffffffffu, d3, off);
        d4 += __shfl_down_sync(0xffffffffu, d4, off);
    }
    if (tx == 0) {
        red[threadIdx.y][0] = d0; red[threadIdx.y][1] = d1; red[threadIdx.y][2] = d2;
        red[threadIdx.y][3] = d3; red[threadIdx.y][4] = d4;
    }
    __syncthreads();
    if (tid < 5) {
        double s = 0.0;
        #pragma unroll
        for (int wi = 0; wi < 8; wi++) s += red[wi][tid];
        g_part[((size_t)img * 256 + by * 16 + bx) * 5 + tid] = s;
    }
}

// ---------------- kernel 2: hysteresis (2 CTAs/image, halo overlap) -------------
__global__ void __launch_bounds__(HY_THREADS) k_hyst(const float* __restrict__ W1,
                                                     const float* __restrict__ b1,
                                                     const float* __restrict__ W2,
                                                     const float* __restrict__ b2,
                                                     float* __restrict__ out) {
    const int img  = blockIdx.x >> 1;
    const int half = blockIdx.x & 1;
    const int r = threadIdx.x;                       // 0..287
    const int start = half ? (H - HY_ROWS) : 0;      // 0 or 232
    const int gr = start + r;
    const bool act = r < HY_ROWS;
    const bool core = act && (half ? (gr >= 256) : (gr < 256));

    __shared__ unsigned int hd[HY_ROWS * HD_STRIDE];  // 19040 B
    __shared__ double sred[8][5];
    __shared__ float sh[32];
    __shared__ float sfeat[5];
    __shared__ int sticket;

    unsigned int Wk[16], E[16], Hh[16];
    if (act) {
        const uint4* wp = reinterpret_cast<const uint4*>(g_weak   + (size_t)img * H * WORDS + gr * WORDS);
        const uint4* sp = reinterpret_cast<const uint4*>(g_strong + (size_t)img * H * WORDS + gr * WORDS);
        #pragma unroll
        for (int q = 0; q < 4; q++) {
            uint4 v = wp[q]; Wk[4*q]=v.x; Wk[4*q+1]=v.y; Wk[4*q+2]=v.z; Wk[4*q+3]=v.w;
            uint4 u = sp[q]; E [4*q]=u.x; E [4*q+1]=u.y; E [4*q+2]=u.z; E [4*q+3]=u.w;
        }
    } else {
        #pragma unroll
        for (int k = 0; k < 16; k++) { Wk[k] = 0u; E[k] = 0u; }
    }

    // Jacobi hysteresis; halo of 24 rows makes core rows bit-exact after <=16 iters
    for (int it = 0; it < 16; it++) {
        if (act) {
            #pragma unroll
            for (int k = 0; k < 16; k++) {
                unsigned int l  = k        ? E[k-1] : 0u;
                unsigned int rt = (k < 15) ? E[k+1] : 0u;
                Hh[k] = E[k] | (E[k] << 1) | (E[k] >> 1) | (l >> 31) | (rt << 31);
                hd[r * HD_STRIDE + k] = Hh[k];
            }
        }
        __syncthreads();
        unsigned int chg = 0;
        if (act) {
            #pragma unroll
            for (int k = 0; k < 16; k++) {
                unsigned int up = r                ? hd[(r-1) * HD_STRIDE + k] : 0u;
                unsigned int dn = (r < HY_ROWS-1)  ? hd[(r+1) * HD_STRIDE + k] : 0u;
                unsigned int ne = Wk[k] & (Hh[k] | up | dn);
                chg |= ne ^ E[k];
                E[k] = ne;
            }
        }
        if (!__syncthreads_or((int)(chg != 0u))) break;
    }

    int ec = 0;
    if (core) {
        #pragma unroll
        for (int k = 0; k < 16; k++) ec += __popc(E[k]);
    }

    // final dilation (no weak mask) for continuity numerator
    if (act) {
        #pragma unroll
        for (int k = 0; k < 16; k++) {
            unsigned int l  = k        ? E[k-1] : 0u;
            unsigned int rt = (k < 15) ? E[k+1] : 0u;
            Hh[k] = E[k] | (E[k] << 1) | (E[k] >> 1) | (l >> 31) | (rt << 31);
            hd[r * HD_STRIDE + k] = Hh[k];
        }
    }
    __syncthreads();
    int dc = 0;
    if (core) {
        #pragma unroll
        for (int k = 0; k < 16; k++) {
            unsigned int up = r               ? hd[(r-1) * HD_STRIDE + k] : 0u;
            unsigned int dn = (r < HY_ROWS-1) ? hd[(r+1) * HD_STRIDE + k] : 0u;
            dc += __popc(Hh[k] | up | dn);
        }
    }

    #pragma unroll
    for (int off = 16; off; off >>= 1) {
        ec += __shfl_down_sync(0xffffffffu, ec, off);
        dc += __shfl_down_sync(0xffffffffu, dc, off);
    }
    if ((r & 31) == 0) {
        if (ec) atomicAdd(&g_cnt[img * 2 + 0], (unsigned)ec);
        if (dc) atomicAdd(&g_cnt[img * 2 + 1], (unsigned)dc);
    }
    __threadfence();
    __syncthreads();
    if (r == 0) sticket = atomicAdd(&g_sync[img], 1);
    __syncthreads();

    // second-finishing CTA does stat reduce + features + MLP (deterministic math)
    if (sticket == 1) {
        double p0 = 0, p1 = 0, p2 = 0, p3 = 0, p4 = 0;
        if (r < 256) {
            const double* pp = g_part + ((size_t)img * 256 + r) * 5;
            p0 = pp[0]; p1 = pp[1]; p2 = pp[2]; p3 = pp[3]; p4 = pp[4];
        }
        #pragma unroll
        for (int off = 16; off; off >>= 1) {
            p0 += __shfl_down_sync(0xffffffffu, p0, off);
            p1 += __shfl_down_sync(0xffffffffu, p1, off);
            p2 += __shfl_down_sync(0xffffffffu, p2, off);
            p3 += __shfl_down_sync(0xffffffffu, p3, off);
            p4 += __shfl_down_sync(0xffffffffu, p4, off);
        }
        if ((r & 31) == 0 && r < 256) {
            int wi = r >> 5;
            sred[wi][0] = p0; sred[wi][1] = p1; sred[wi][2] = p2;
            sred[wi][3] = p3; sred[wi][4] = p4;
        }
        __syncthreads();
        if (r == 0) {
            double s0 = 0, s1 = 0, s2 = 0, s3 = 0, s4 = 0;
            #pragma unroll
            for (int wi = 0; wi < 8; wi++) {
                s0 += sred[wi][0]; s1 += sred[wi][1]; s2 += sred[wi][2];
                s3 += sred[wi][3]; s4 += sred[wi][4];
            }
            unsigned uec = atomicAdd(&g_cnt[img * 2 + 0], 0u);
            unsigned udc = atomicAdd(&g_cnt[img * 2 + 1], 0u);
            const double inv = 1.0 / (double)HW;
            sfeat[0] = (float)uec / (float)HW;
            sfeat[1] = (float)(s0 * inv / 255.0);
            sfeat[2] = (float)udc / ((float)uec + 1e-10f);
            double am = s1 * inv;
            sfeat[3] = (float)(s2 * inv - am * am);
            double lm = s3 * inv;
            sfeat[4] = (float)((s4 * inv - lm * lm) / 1000.0);
        }
        __syncthreads();
        if (r < 32) {
            float acc = b1[r];
            #pragma unroll
            for (int f = 0; f < 5; f++) acc += sfeat[f] * W1[f * 32 + r];
            sh[r] = fmaxf(acc, 0.0f);
        }
        __syncthreads();
        if (r < 64) {
            float acc = b2[r];
            #pragma unroll
            for (int j = 0; j < 32; j++) acc += sh[j] * W2[j * 64 + r];
            out[img * 64 + r] = fmaxf(acc, 0.0f);
        }
    }
}

// ---------------- launch ---------------------------------------------------------
extern "C" void kernel_launch(void* const* d_in, const int* in_sizes, int n_in,
                              void* d_out, int out_size) {
    const float* x  = (const float*)d_in[0];
    const float* W1 = (const float*)d_in[1];
    const float* b1 = (const float*)d_in[2];
    const float* W2 = (const float*)d_in[3];
    const float* b2 = (const float*)d_in[4];
    float* out = (float*)d_out;

    dim3 g2(16, 16, IMGS), t2(32, 8);
    k_sobel<<<g2, t2>>>(x);
    k_hyst<<<IMGS * 2, HY_THREADS>>>(W1, b1, W2, b2, out);
}